// round 9
// baseline (speedup 1.0000x reference)
#include <cuda_runtime.h>

// Problem constants (fixed by the reference: B=2, C=8, L=256, D=128)
#define B_  2
#define C_  8
#define L_  256
#define D_  128
#define TILE 32          // 32x32 output tile per block
#define THREADS 128      // 16 (ti: row-pairs) x 8 (tj: col-quads); 2x4 out each

using u64 = unsigned long long;

// ---- packed f32x2 helpers (sm_100a) ----
__device__ __forceinline__ u64 pack2(float lo, float hi) {
    u64 r; asm("mov.b64 %0, {%1, %2};" : "=l"(r) : "f"(lo), "f"(hi)); return r;
}
__device__ __forceinline__ float2 unpack2(u64 v) {
    float lo, hi; asm("mov.b64 {%0, %1}, %2;" : "=f"(lo), "=f"(hi) : "l"(v));
    return make_float2(lo, hi);
}
__device__ __forceinline__ u64 fma2_(u64 a, u64 b, u64 c) {
    u64 d; asm("fma.rn.f32x2 %0, %1, %2, %3;" : "=l"(d) : "l"(a), "l"(b), "l"(c)); return d;
}
__device__ __forceinline__ u64 mul2_(u64 a, u64 b) {
    u64 d; asm("mul.rn.f32x2 %0, %1, %2;" : "=l"(d) : "l"(a), "l"(b)); return d;
}
__device__ __forceinline__ float rcp_fast(float x) {
    float y; asm("rcp.approx.f32 %0, %1;" : "=f"(y) : "f"(x)); return y;
}
__device__ __forceinline__ float ex2_fast(float x) {
    float y; asm("ex2.approx.f32 %0, %1;" : "=f"(y) : "f"(x)); return y;
}

// Integer magic reciprocal seed on both packed halves (max rel err ~3.4%).
__device__ __forceinline__ u64 seed2(u64 x) {
    unsigned lo = (unsigned)x, hi = (unsigned)(x >> 32);
    return (u64)(0x7EF311C3u - lo) | ((u64)(0x7EF311C3u - hi) << 32);
}
// Packed Newton: returns y ~= -1/x (NEGATIVE), x > 0 in both halves.
// y1 = y0*(x*y0 - 2) ~= -1/x ; y2 = y1*(x*y1 + 2) ~= -1/x (quadratic)
__device__ __forceinline__ u64 nrcp2(u64 x, u64 TWO2, u64 NTWO2) {
    u64 y0 = seed2(x);
    u64 y1 = mul2_(y0, fma2_(x, y0, NTWO2));
    return  mul2_(y1, fma2_(x, y1, TWO2));
}

#define TWO_LOG2E 2.885390081777927f   // 2 * log2(e)

// smem: At[d][i] = exp(2*s), Bt[d][j] = exp(2*e), both f32 (16 KB each).
// vp[d2] = ( +v[2*d2], -v[2*d2+1] ) ; vsum = sum_d v[d].
__global__ __launch_bounds__(THREADS)
void Add_Attn_Layer_59055800320841_kernel(const float* __restrict__ S,
                                          const float* __restrict__ E,
                                          const float* __restrict__ V,
                                          float* __restrict__ out) {
    __shared__ float  At[D_ * TILE];
    __shared__ float  Bt[D_ * TILE];
    __shared__ float2 vp[D_ / 2];
    __shared__ float  vsum_s;

    const int bc = blockIdx.z;            // b*C + c   (0..15)
    const int i0 = blockIdx.y * TILE;
    const int j0 = blockIdx.x * TILE;

    const float* Sbase = S + (size_t)bc * L_ * D_ + (size_t)i0 * D_;
    const float* Ebase = E + (size_t)bc * L_ * D_ + (size_t)j0 * D_;

    const int tid = threadIdx.x;

    // v: sign-folded pairs + block-wide sum
    if (tid < D_ / 2) {
        const float2 v2 = *reinterpret_cast<const float2*>(V + 2 * tid);
        vp[tid] = make_float2(v2.x, -v2.y);
    }
    if (tid < 32) {
        float s = V[tid] + V[tid + 32] + V[tid + 64] + V[tid + 96];
        #pragma unroll
        for (int o = 16; o > 0; o >>= 1) s += __shfl_xor_sync(0xffffffffu, s, o);
        if (tid == 0) vsum_s = s;
    }

    // Load + transpose + exponentiate: At[d][row] = exp(2*s(row,d)).
    #pragma unroll
    for (int idx = tid; idx < TILE * (D_ / 4); idx += THREADS) {
        const int row = idx & (TILE - 1);
        const int d4  = idx >> 5;                 // d = 4*d4 + q
        const float4 sv = *reinterpret_cast<const float4*>(Sbase + row * D_ + d4 * 4);
        const float4 ev = *reinterpret_cast<const float4*>(Ebase + row * D_ + d4 * 4);
        At[(4 * d4 + 0) * TILE + row] = ex2_fast(sv.x * TWO_LOG2E);
        At[(4 * d4 + 1) * TILE + row] = ex2_fast(sv.y * TWO_LOG2E);
        At[(4 * d4 + 2) * TILE + row] = ex2_fast(sv.z * TWO_LOG2E);
        At[(4 * d4 + 3) * TILE + row] = ex2_fast(sv.w * TWO_LOG2E);
        Bt[(4 * d4 + 0) * TILE + row] = ex2_fast(ev.x * TWO_LOG2E);
        Bt[(4 * d4 + 1) * TILE + row] = ex2_fast(ev.y * TWO_LOG2E);
        Bt[(4 * d4 + 2) * TILE + row] = ex2_fast(ev.z * TWO_LOG2E);
        Bt[(4 * d4 + 3) * TILE + row] = ex2_fast(ev.w * TWO_LOG2E);
    }
    __syncthreads();

    // Thread -> 2 rows (il..il+1) x 4 cols (jl..jl+3)
    const int tj = tid & 7;
    const int ti = tid >> 3;
    const int il = 2 * ti;
    const int jl = 4 * tj;

    const u64 ONE2  = pack2(1.0f, 1.0f);
    const u64 TWO2  = pack2(2.0f, 2.0f);
    const u64 NTWO2 = pack2(-2.0f, -2.0f);

    // Packed accumulators: Σ v_d / (1 + A_i,d * B_j,d)
    u64 acc00 = 0, acc01 = 0, acc10 = 0, acc11 = 0;   // bits of (0.f,0.f)

    #pragma unroll 2
    for (int d2 = 0; d2 < D_ / 2; d2++) {
        const float2 v2 = vp[d2];

        // ---------- even d = 2*d2 : MUFU rcp path ----------
        {
            const int d = 2 * d2;
            const float2 a = *reinterpret_cast<const float2*>(&At[d * TILE + il]);
            const float4 b = *reinterpret_cast<const float4*>(&Bt[d * TILE + jl]);
            const float y00 = rcp_fast(fmaf(a.x, b.x, 1.0f));
            const float y01 = rcp_fast(fmaf(a.x, b.y, 1.0f));
            const float y02 = rcp_fast(fmaf(a.x, b.z, 1.0f));
            const float y03 = rcp_fast(fmaf(a.x, b.w, 1.0f));
            const float y10 = rcp_fast(fmaf(a.y, b.x, 1.0f));
            const float y11 = rcp_fast(fmaf(a.y, b.y, 1.0f));
            const float y12 = rcp_fast(fmaf(a.y, b.z, 1.0f));
            const float y13 = rcp_fast(fmaf(a.y, b.w, 1.0f));
            const u64 ve = pack2(v2.x, v2.x);           // +v (y positive)
            acc00 = fma2_(ve, pack2(y00, y01), acc00);
            acc01 = fma2_(ve, pack2(y02, y03), acc01);
            acc10 = fma2_(ve, pack2(y10, y11), acc10);
            acc11 = fma2_(ve, pack2(y12, y13), acc11);
        }
        // ---------- odd d = 2*d2+1 : packed Newton path ----------
        {
            const int d = 2 * d2 + 1;
            const float2 a = *reinterpret_cast<const float2*>(&At[d * TILE + il]);
            const ulonglong2 bq = *reinterpret_cast<const ulonglong2*>(&Bt[d * TILE + jl]);
            const u64 as0 = pack2(a.x, a.x);
            const u64 as1 = pack2(a.y, a.y);
            const u64 x00 = fma2_(as0, bq.x, ONE2);     // 1 + a0*(b0,b1)
            const u64 x01 = fma2_(as0, bq.y, ONE2);
            const u64 x10 = fma2_(as1, bq.x, ONE2);
            const u64 x11 = fma2_(as1, bq.y, ONE2);
            const u64 vo = pack2(v2.y, v2.y);           // -v (y negative)
            acc00 = fma2_(vo, nrcp2(x00, TWO2, NTWO2), acc00);
            acc01 = fma2_(vo, nrcp2(x01, TWO2, NTWO2), acc01);
            acc10 = fma2_(vo, nrcp2(x10, TWO2, NTWO2), acc10);
            acc11 = fma2_(vo, nrcp2(x11, TWO2, NTWO2), acc11);
        }
    }

    // out = vsum - 2 * acc   (tanh(s+e) = 1 - 2/(1+exp(2s+2e)))
    const float vsum = vsum_s;
    const float2 r00 = unpack2(acc00), r01 = unpack2(acc01);
    const float2 r10 = unpack2(acc10), r11 = unpack2(acc11);

    const int b = bc >> 3;
    const int c = bc & 7;
    const int i = i0 + il;
    const int j = j0 + jl;
    float* o = out + (((size_t)b * L_ + i) * L_ + j) * C_ + c;
    const size_t rs = (size_t)L_ * C_;   // i -> i+1
    o[0 * C_]      = fmaf(-2.0f, r00.x, vsum);
    o[1 * C_]      = fmaf(-2.0f, r00.y, vsum);
    o[2 * C_]      = fmaf(-2.0f, r01.x, vsum);
    o[3 * C_]      = fmaf(-2.0f, r01.y, vsum);
    o[rs + 0 * C_] = fmaf(-2.0f, r10.x, vsum);
    o[rs + 1 * C_] = fmaf(-2.0f, r10.y, vsum);
    o[rs + 2 * C_] = fmaf(-2.0f, r11.x, vsum);
    o[rs + 3 * C_] = fmaf(-2.0f, r11.y, vsum);
}

extern "C" void kernel_launch(void* const* d_in, const int* in_sizes, int n_in,
                              void* d_out, int out_size) {
    (void)in_sizes; (void)n_in; (void)out_size;
    const float* S = (const float*)d_in[0];   // start_hidden [B,C,L,D]
    const float* E = (const float*)d_in[1];   // end_hidden   [B,C,L,D]
    const float* V = (const float*)d_in[2];   // v [D]
    float* out = (float*)d_out;               // [B,L,L,C] float32

    dim3 grid(L_ / TILE, L_ / TILE, B_ * C_); // (8, 8, 16) = 1024 blocks
    Add_Attn_Layer_59055800320841_kernel<<<grid, THREADS>>>(S, E, V, out);
}

// round 10
// speedup vs baseline: 1.0430x; 1.0430x over previous
#include <cuda_runtime.h>

// Problem constants (fixed by the reference: B=2, C=8, L=256, D=128)
#define B_  2
#define C_  8
#define L_  256
#define D_  128
#define TILE 32          // 32x32 output tile per block
#define THREADS 256      // 16 (ti: row-pairs) x 16 (tj: col-pairs); 2x2 out each

using u64 = unsigned long long;

// ---- packed f32x2 helpers (sm_100a) ----
__device__ __forceinline__ u64 pack2(float lo, float hi) {
    u64 r; asm("mov.b64 %0, {%1, %2};" : "=l"(r) : "f"(lo), "f"(hi)); return r;
}
__device__ __forceinline__ float2 unpack2(u64 v) {
    float lo, hi; asm("mov.b64 {%0, %1}, %2;" : "=f"(lo), "=f"(hi) : "l"(v));
    return make_float2(lo, hi);
}
__device__ __forceinline__ u64 fma2_(u64 a, u64 b, u64 c) {
    u64 d; asm("fma.rn.f32x2 %0, %1, %2, %3;" : "=l"(d) : "l"(a), "l"(b), "l"(c)); return d;
}
__device__ __forceinline__ u64 mul2_(u64 a, u64 b) {
    u64 d; asm("mul.rn.f32x2 %0, %1, %2;" : "=l"(d) : "l"(a), "l"(b)); return d;
}
__device__ __forceinline__ float rcp_fast(float x) {
    float y; asm("rcp.approx.f32 %0, %1;" : "=f"(y) : "f"(x)); return y;
}
__device__ __forceinline__ float ex2_fast(float x) {
    float y; asm("ex2.approx.f32 %0, %1;" : "=f"(y) : "f"(x)); return y;
}

// Packed magic reciprocal seed in ONE 64-bit subtract (2x IADD3 in SASS).
// Valid because x = 1 + A*B  =>  f32 bits in [0x3F800000, ~0x4C000000],
// strictly below 0x7EF311C3, so the low-half subtract never borrows.
__device__ __forceinline__ u64 seed2(u64 x) {
    return 0x7EF311C37EF311C3ull - x;
}
// Packed Newton (2 iters): returns y ~= -1/x (NEGATIVE), x > 0 in both halves.
// y1 = y0*(x*y0 - 2) ~= -1/x ; y2 = y1*(x*y1 + 2) (quadratic convergence)
__device__ __forceinline__ u64 nrcp2(u64 x, u64 TWO2, u64 NTWO2) {
    u64 y0 = seed2(x);
    u64 y1 = mul2_(y0, fma2_(x, y0, NTWO2));
    return  mul2_(y1, fma2_(x, y1, TWO2));
}

#define TWO_LOG2E 2.885390081777927f   // 2 * log2(e)

// smem: At[d][i] = exp(2*s), Bt[d][j] = exp(2*e), both f32 (16 KB each).
// vp[d2] = ( +v[2*d2], -v[2*d2+1] ) ; vsum = sum_d v[d].
// tanh(s+e) = 1 - 2/(1 + exp(2s)exp(2e))  =>  out = vsum - 2 * sum_d v_d/(1+A·B)
__global__ __launch_bounds__(THREADS)
void Add_Attn_Layer_59055800320841_kernel(const float* __restrict__ S,
                                          const float* __restrict__ E,
                                          const float* __restrict__ V,
                                          float* __restrict__ out) {
    __shared__ float  At[D_ * TILE];
    __shared__ float  Bt[D_ * TILE];
    __shared__ float2 vp[D_ / 2];
    __shared__ float  vsum_s;

    const int bc = blockIdx.z;            // b*C + c   (0..15)
    const int i0 = blockIdx.y * TILE;
    const int j0 = blockIdx.x * TILE;

    const float* Sbase = S + (size_t)bc * L_ * D_ + (size_t)i0 * D_;
    const float* Ebase = E + (size_t)bc * L_ * D_ + (size_t)j0 * D_;

    const int tid = threadIdx.x;

    // v: sign-folded pairs + block-wide sum
    if (tid < D_ / 2) {
        const float2 v2 = *reinterpret_cast<const float2*>(V + 2 * tid);
        vp[tid] = make_float2(v2.x, -v2.y);
    }
    if (tid < 32) {
        float s = V[tid] + V[tid + 32] + V[tid + 64] + V[tid + 96];
        #pragma unroll
        for (int o = 16; o > 0; o >>= 1) s += __shfl_xor_sync(0xffffffffu, s, o);
        if (tid == 0) vsum_s = s;
    }

    // Load + transpose + exponentiate: At[d][row] = exp(2*s(row,d)).
    #pragma unroll
    for (int idx = tid; idx < TILE * (D_ / 4); idx += THREADS) {
        const int row = idx & (TILE - 1);
        const int d4  = idx >> 5;                 // d = 4*d4 + q
        const float4 sv = *reinterpret_cast<const float4*>(Sbase + row * D_ + d4 * 4);
        const float4 ev = *reinterpret_cast<const float4*>(Ebase + row * D_ + d4 * 4);
        At[(4 * d4 + 0) * TILE + row] = ex2_fast(sv.x * TWO_LOG2E);
        At[(4 * d4 + 1) * TILE + row] = ex2_fast(sv.y * TWO_LOG2E);
        At[(4 * d4 + 2) * TILE + row] = ex2_fast(sv.z * TWO_LOG2E);
        At[(4 * d4 + 3) * TILE + row] = ex2_fast(sv.w * TWO_LOG2E);
        Bt[(4 * d4 + 0) * TILE + row] = ex2_fast(ev.x * TWO_LOG2E);
        Bt[(4 * d4 + 1) * TILE + row] = ex2_fast(ev.y * TWO_LOG2E);
        Bt[(4 * d4 + 2) * TILE + row] = ex2_fast(ev.z * TWO_LOG2E);
        Bt[(4 * d4 + 3) * TILE + row] = ex2_fast(ev.w * TWO_LOG2E);
    }
    __syncthreads();

    // Thread -> 2 rows (il, il+1) x 2 cols (jl, jl+1)
    const int tj = tid & 15;
    const int ti = tid >> 4;
    const int il = 2 * ti;
    const int jl = 2 * tj;

    const u64 ONE2  = pack2(1.0f, 1.0f);
    const u64 TWO2  = pack2(2.0f, 2.0f);
    const u64 NTWO2 = pack2(-2.0f, -2.0f);

    // Even-d path: scalar f32 accumulators (MUFU rcp, no packing MOVs).
    float e00 = 0.f, e01 = 0.f, e10 = 0.f, e11 = 0.f;
    // Odd-d path: packed accumulators over columns (c0,c1), negative-y side.
    u64 acc0 = 0, acc1 = 0;                     // bits of (0.f, 0.f)

    #pragma unroll 4
    for (int d2 = 0; d2 < D_ / 2; d2++) {
        const float2 va = vp[d2];               // (+v_even, -v_odd)

        // ---------- even d = 2*d2 : MUFU rcp, scalar ----------
        {
            const float2 a = *reinterpret_cast<const float2*>(&At[(2 * d2) * TILE + il]);
            const float2 b = *reinterpret_cast<const float2*>(&Bt[(2 * d2) * TILE + jl]);
            e00 = fmaf(va.x, rcp_fast(fmaf(a.x, b.x, 1.0f)), e00);
            e01 = fmaf(va.x, rcp_fast(fmaf(a.x, b.y, 1.0f)), e01);
            e10 = fmaf(va.x, rcp_fast(fmaf(a.y, b.x, 1.0f)), e10);
            e11 = fmaf(va.x, rcp_fast(fmaf(a.y, b.y, 1.0f)), e11);
        }
        // ---------- odd d = 2*d2+1 : packed Newton ----------
        {
            const float2 a = *reinterpret_cast<const float2*>(&At[(2 * d2 + 1) * TILE + il]);
            const u64    b = *reinterpret_cast<const u64*>(&Bt[(2 * d2 + 1) * TILE + jl]);
            const u64 x0 = fma2_(pack2(a.x, a.x), b, ONE2);   // row0: 1 + a0*(b0,b1)
            const u64 x1 = fma2_(pack2(a.y, a.y), b, ONE2);   // row1
            const u64 vo = pack2(va.y, va.y);                 // -v (y negative)
            acc0 = fma2_(vo, nrcp2(x0, TWO2, NTWO2), acc0);
            acc1 = fma2_(vo, nrcp2(x1, TWO2, NTWO2), acc1);
        }
    }

    // Combine: total = even + odd ; out = vsum - 2 * total
    const float vsum = vsum_s;
    const float2 o0 = unpack2(acc0);
    const float2 o1 = unpack2(acc1);
    const float t00 = e00 + o0.x, t01 = e01 + o0.y;
    const float t10 = e10 + o1.x, t11 = e11 + o1.y;

    const int b = bc >> 3;
    const int c = bc & 7;
    const int i = i0 + il;
    const int j = j0 + jl;
    float* o = out + (((size_t)b * L_ + i) * L_ + j) * C_ + c;
    const size_t rs = (size_t)L_ * C_;   // i -> i+1
    o[0]       = fmaf(-2.0f, t00, vsum);
    o[C_]      = fmaf(-2.0f, t01, vsum);
    o[rs]      = fmaf(-2.0f, t10, vsum);
    o[rs + C_] = fmaf(-2.0f, t11, vsum);
}

extern "C" void kernel_launch(void* const* d_in, const int* in_sizes, int n_in,
                              void* d_out, int out_size) {
    (void)in_sizes; (void)n_in; (void)out_size;
    const float* S = (const float*)d_in[0];   // start_hidden [B,C,L,D]
    const float* E = (const float*)d_in[1];   // end_hidden   [B,C,L,D]
    const float* V = (const float*)d_in[2];   // v [D]
    float* out = (float*)d_out;               // [B,L,L,C] float32

    dim3 grid(L_ / TILE, L_ / TILE, B_ * C_); // (8, 8, 16) = 1024 blocks
    Add_Attn_Layer_59055800320841_kernel<<<grid, THREADS>>>(S, E, V, out);
}

// round 11
// speedup vs baseline: 1.0766x; 1.0323x over previous
#include <cuda_runtime.h>

// Problem constants (fixed by the reference: B=2, C=8, L=256, D=128)
#define B_  2
#define C_  8
#define L_  256
#define D_  128
#define TILE 32          // 32x32 output tile per block
#define THREADS 256      // 16 (ti: row-pairs) x 16 (tj: col-pairs); 2x2 out each

using u64 = unsigned long long;

// ---- packed f32x2 helpers (sm_100a) ----
__device__ __forceinline__ u64 pack2(float lo, float hi) {
    u64 r; asm("mov.b64 %0, {%1, %2};" : "=l"(r) : "f"(lo), "f"(hi)); return r;
}
__device__ __forceinline__ float2 unpack2(u64 v) {
    float lo, hi; asm("mov.b64 {%0, %1}, %2;" : "=f"(lo), "=f"(hi) : "l"(v));
    return make_float2(lo, hi);
}
__device__ __forceinline__ u64 fma2_(u64 a, u64 b, u64 c) {
    u64 d; asm("fma.rn.f32x2 %0, %1, %2, %3;" : "=l"(d) : "l"(a), "l"(b), "l"(c)); return d;
}
__device__ __forceinline__ u64 mul2_(u64 a, u64 b) {
    u64 d; asm("mul.rn.f32x2 %0, %1, %2;" : "=l"(d) : "l"(a), "l"(b)); return d;
}
__device__ __forceinline__ float rcp_fast(float x) {
    float y; asm("rcp.approx.f32 %0, %1;" : "=f"(y) : "f"(x)); return y;
}
__device__ __forceinline__ float ex2_fast(float x) {
    float y; asm("ex2.approx.f32 %0, %1;" : "=f"(y) : "f"(x)); return y;
}

// Packed magic reciprocal seed in ONE 64-bit subtract.
// Valid: x = 1 + A*B has f32 bits in [0x3F800000, ~0x4C000000], below
// 0x7EF311C3, so the low-half subtract never borrows into the high half.
__device__ __forceinline__ u64 seed2(u64 x) {
    return 0x7EF311C37EF311C3ull - x;
}
// Packed Newton (2 iters): y ~= -1/x (NEGATIVE), x > 0 in both halves.
__device__ __forceinline__ u64 nrcp2(u64 x, u64 TWO2, u64 NTWO2) {
    u64 y0 = seed2(x);
    u64 y1 = mul2_(y0, fma2_(x, y0, NTWO2));
    return  mul2_(y1, fma2_(x, y1, TWO2));
}

#define TWO_LOG2E 2.885390081777927f   // 2 * log2(e)

// tanh(s+e) = 1 - 2/(1 + exp(2s)exp(2e))  =>  out = vsum - 2 * Σ_d v_d/(1+A·B)
// smem:
//   Aev[d2][i]  f32  A for even d = 2*d2                    (8 KB)
//   Asp[d2][i]  u64  (A,A) splatted, for odd d = 2*d2+1     (16 KB)
//   Bt [d][j]   f32  B for all d                            (16 KB)
//   vev[d2] = +v[2*d2] ; vod[d2] = packed (-v[2*d2+1], -v[2*d2+1])
__global__ __launch_bounds__(THREADS)
void Add_Attn_Layer_59055800320841_kernel(const float* __restrict__ S,
                                          const float* __restrict__ E,
                                          const float* __restrict__ V,
                                          float* __restrict__ out) {
    __shared__ float Aev[(D_ / 2) * TILE];
    __shared__ u64   Asp[(D_ / 2) * TILE];
    __shared__ float Bt[D_ * TILE];
    __shared__ float vev[D_ / 2];
    __shared__ u64   vod[D_ / 2];
    __shared__ float vsum_s;

    const int bc = blockIdx.z;            // b*C + c   (0..15)
    const int i0 = blockIdx.y * TILE;
    const int j0 = blockIdx.x * TILE;

    const float* Sbase = S + (size_t)bc * L_ * D_ + (size_t)i0 * D_;
    const float* Ebase = E + (size_t)bc * L_ * D_ + (size_t)j0 * D_;

    const int tid = threadIdx.x;

    // v: split even/odd, pre-packed; plus block-wide sum.
    if (tid < D_ / 2) {
        const float2 v2 = *reinterpret_cast<const float2*>(V + 2 * tid);
        vev[tid] = v2.x;
        vod[tid] = pack2(-v2.y, -v2.y);
    }
    if (tid < 32) {
        float s = V[tid] + V[tid + 32] + V[tid + 64] + V[tid + 96];
        #pragma unroll
        for (int o = 16; o > 0; o >>= 1) s += __shfl_xor_sync(0xffffffffu, s, o);
        if (tid == 0) vsum_s = s;
    }

    // Load + transpose + exponentiate. A split even/odd (odd pre-splatted).
    #pragma unroll
    for (int idx = tid; idx < TILE * (D_ / 4); idx += THREADS) {
        const int row = idx & (TILE - 1);
        const int d4  = idx >> 5;                 // d = 4*d4 + q
        const float4 sv = *reinterpret_cast<const float4*>(Sbase + row * D_ + d4 * 4);
        const float4 ev = *reinterpret_cast<const float4*>(Ebase + row * D_ + d4 * 4);
        const float a0 = ex2_fast(sv.x * TWO_LOG2E);   // d = 4d4   (even, d2=2d4)
        const float a1 = ex2_fast(sv.y * TWO_LOG2E);   // d = 4d4+1 (odd,  d2=2d4)
        const float a2 = ex2_fast(sv.z * TWO_LOG2E);   // d = 4d4+2 (even, d2=2d4+1)
        const float a3 = ex2_fast(sv.w * TWO_LOG2E);   // d = 4d4+3 (odd,  d2=2d4+1)
        Aev[(2 * d4 + 0) * TILE + row] = a0;
        Asp[(2 * d4 + 0) * TILE + row] = pack2(a1, a1);
        Aev[(2 * d4 + 1) * TILE + row] = a2;
        Asp[(2 * d4 + 1) * TILE + row] = pack2(a3, a3);
        Bt[(4 * d4 + 0) * TILE + row] = ex2_fast(ev.x * TWO_LOG2E);
        Bt[(4 * d4 + 1) * TILE + row] = ex2_fast(ev.y * TWO_LOG2E);
        Bt[(4 * d4 + 2) * TILE + row] = ex2_fast(ev.z * TWO_LOG2E);
        Bt[(4 * d4 + 3) * TILE + row] = ex2_fast(ev.w * TWO_LOG2E);
    }
    __syncthreads();

    // Thread -> 2 rows (il, il+1) x 2 cols (jl, jl+1)
    const int tj = tid & 15;
    const int ti = tid >> 4;
    const int il = 2 * ti;
    const int jl = 2 * tj;

    const u64 ONE2  = pack2(1.0f, 1.0f);
    const u64 TWO2  = pack2(2.0f, 2.0f);
    const u64 NTWO2 = pack2(-2.0f, -2.0f);

    // Even-d: scalar f32 accumulators (MUFU rcp). Odd-d: packed accumulators.
    float e00 = 0.f, e01 = 0.f, e10 = 0.f, e11 = 0.f;
    u64 acc0 = 0, acc1 = 0;                     // bits of (0.f, 0.f)

    const float* aevp = Aev + il;
    const u64*   aspp = Asp + il;
    const float* btp  = Bt + jl;

    #pragma unroll 4
    for (int d2 = 0; d2 < D_ / 2; d2++) {
        // ---------- even d = 2*d2 : MUFU rcp, fully scalar ----------
        {
            const float2 a = *reinterpret_cast<const float2*>(aevp + d2 * TILE);
            const float2 b = *reinterpret_cast<const float2*>(btp + (2 * d2) * TILE);
            const float ve = vev[d2];
            e00 = fmaf(ve, rcp_fast(fmaf(a.x, b.x, 1.0f)), e00);
            e01 = fmaf(ve, rcp_fast(fmaf(a.x, b.y, 1.0f)), e01);
            e10 = fmaf(ve, rcp_fast(fmaf(a.y, b.x, 1.0f)), e10);
            e11 = fmaf(ve, rcp_fast(fmaf(a.y, b.y, 1.0f)), e11);
        }
        // ---------- odd d = 2*d2+1 : packed Newton, zero packs ----------
        {
            const ulonglong2 asp = *reinterpret_cast<const ulonglong2*>(aspp + d2 * TILE);
            const u64 b = *reinterpret_cast<const u64*>(btp + (2 * d2 + 1) * TILE);
            const u64 vo = vod[d2];                        // (-v, -v)
            const u64 x0 = fma2_(asp.x, b, ONE2);          // row0: 1 + a*(b0,b1)
            const u64 x1 = fma2_(asp.y, b, ONE2);          // row1
            acc0 = fma2_(vo, nrcp2(x0, TWO2, NTWO2), acc0);
            acc1 = fma2_(vo, nrcp2(x1, TWO2, NTWO2), acc1);
        }
    }

    // Combine: total = even + odd ; out = vsum - 2 * total
    const float vsum = vsum_s;
    const float2 o0 = unpack2(acc0);
    const float2 o1 = unpack2(acc1);
    const float t00 = e00 + o0.x, t01 = e01 + o0.y;
    const float t10 = e10 + o1.x, t11 = e11 + o1.y;

    const int b = bc >> 3;
    const int c = bc & 7;
    const int i = i0 + il;
    const int j = j0 + jl;
    float* o = out + (((size_t)b * L_ + i) * L_ + j) * C_ + c;
    const size_t rs = (size_t)L_ * C_;   // i -> i+1
    o[0]       = fmaf(-2.0f, t00, vsum);
    o[C_]      = fmaf(-2.0f, t01, vsum);
    o[rs]      = fmaf(-2.0f, t10, vsum);
    o[rs + C_] = fmaf(-2.0f, t11, vsum);
}

extern "C" void kernel_launch(void* const* d_in, const int* in_sizes, int n_in,
                              void* d_out, int out_size) {
    (void)in_sizes; (void)n_in; (void)out_size;
    const float* S = (const float*)d_in[0];   // start_hidden [B,C,L,D]
    const float* E = (const float*)d_in[1];   // end_hidden   [B,C,L,D]
    const float* V = (const float*)d_in[2];   // v [D]
    float* out = (float*)d_out;               // [B,L,L,C] float32

    dim3 grid(L_ / TILE, L_ / TILE, B_ * C_); // (8, 8, 16) = 1024 blocks
    Add_Attn_Layer_59055800320841_kernel<<<grid, THREADS>>>(S, E, V, out);
}